// round 13
// baseline (speedup 1.0000x reference)
#include <cuda_runtime.h>
#include <cstdint>

// Problem constants (fixed by the dataset)
#define DD 16
#define BB 8
#define EE 2048
#define OO 2048

#define ECH    4                 // e's per task (finer tasks for dynamic balance)
#define NCHUNK (EE / ECH)        // 512 tasks per o-tile group
#define NTHREADS 128
#define OTILE  (NTHREADS * 4)    // 512 o's per block
#define NOT    (OO / OTILE)      // 4
#define NWX    259               // workers per o-tile group (259*4 = 1036 = 148*7)
#define PF     4                 // prefetch pipeline depth

__device__ int g_ticket[NOT];    // per-otile dynamic work queues

__global__ __launch_bounds__(256)
void zero_out(float* __restrict__ out) {
    out[blockIdx.x * 256 + threadIdx.x] = 0.0f;
    if (blockIdx.x == 0 && threadIdx.x < NOT) g_ticket[threadIdx.x] = 0;
}

__global__ __launch_bounds__(NTHREADS, 7)
void delta_synapse_main(const float* __restrict__ W,
                        const float* __restrict__ signs,
                        const float* __restrict__ Xd,
                        const float* __restrict__ Wshort,
                        const float* __restrict__ dmap,
                        float* __restrict__ out) {
    __shared__ float    coef[DD * BB][ECH];          // 2 KB: signed Xd*(Wshort+1)
    __shared__ float4   weffs[ECH][NTHREADS];        // 8 KB: raw W slice
    __shared__ uint32_t wl_off [ECH * DD + 2 * PF];  // (d*EE+e)*OO element offset
    __shared__ uint32_t wl_meta[ECH * DD + 2 * PF];  // el | d<<2 | bm<<6
    __shared__ int   s_idx[ECH];
    __shared__ float s_pre[ECH];
    __shared__ int wl_n;
    __shared__ int task_s;

    const int tid   = threadIdx.x;
    const int otile = blockIdx.y;                    // fixed per worker
    const int obase = otile * OTILE + tid * 4;
    const float* dbase = dmap + obase;

    float4 acc[BB];                                  // persists across tasks
    #pragma unroll
    for (int b = 0; b < BB; b++) acc[b] = make_float4(0.f, 0.f, 0.f, 0.f);

    for (;;) {
        if (tid == 0) task_s = atomicAdd(&g_ticket[otile], 1);
        __syncthreads();                             // also fences smem reuse
        const int chunk = task_s;
        if (chunk >= NCHUNK) break;
        const int e0 = chunk * ECH;

        if (tid == 0) wl_n = 0;
        if (tid < ECH) s_idx[tid] = 0;

        // ---- Phase 1: coef[d*8+b][el] = Xd*(Wshort+1)  (512 elems, 4/thread)
        #pragma unroll
        for (int r = 0; r < (DD * BB * ECH) / NTHREADS; r++) {
            const int idx = r * NTHREADS + tid;
            const int el  = idx & (ECH - 1);
            const int g   = idx >> 2;                // d*8 + b
            const int gi  = g * EE + e0 + el;
            const float x = Xd[gi];
            coef[g][el] = x * (Wshort[gi] + 1.0f);
        }
        __syncthreads();

        // ---- Phase 2: (el,d) pairs = 64; warp-aggregated append (warps 0-1)
        if (tid < ECH * DD) {
            const int el = tid & (ECH - 1);
            const int d  = tid >> 2;                 // 0..15
            unsigned bm = 0;
            #pragma unroll
            for (int b = 0; b < BB; b++)
                if (coef[d * BB + b][el] != 0.0f) bm |= 1u << b;
            const unsigned act  = __ballot_sync(0xffffffffu, bm != 0);
            const int      lane = tid & 31;
            int base = 0;
            if (lane == 0 && act) base = atomicAdd(&wl_n, __popc(act));
            base = __shfl_sync(0xffffffffu, base, 0);
            if (bm) {
                const int pos = base + __popc(act & ((1u << lane) - 1u));
                wl_off [pos] = (uint32_t)(d * EE + e0 + el) * OO;
                wl_meta[pos] = (uint32_t)(el | (d << 2) | (bm << 6));
            }
        }
        __syncthreads();

        const int n0   = wl_n;
        const int npad = (n0 + PF - 1) & ~(PF - 1);
        if (tid < 2 * PF) { wl_off[n0 + tid] = 0u; wl_meta[n0 + tid] = 0u; }
        __syncthreads();

        // ---- Early dmap prefetch overlaps the W-load phase
        float4 buf[PF];
        #pragma unroll
        for (int j = 0; j < PF; j++)
            buf[j] = __ldcs((const float4*)(dbase + wl_off[j]));

        // ---- Phase 3a: raw W into smem; record any positive-W o (racy OK)
        #pragma unroll
        for (int el = 0; el < ECH; el++) {
            const float4 wv = __ldcs((const float4*)&W[(size_t)(e0 + el) * OO + obase]);
            weffs[el][tid] = wv;
            if (wv.x > 0.f || wv.y > 0.f || wv.z > 0.f || wv.w > 0.f) {
                const int c = wv.x > 0.f ? 0 : (wv.y > 0.f ? 1 : (wv.z > 0.f ? 2 : 3));
                s_idx[el] = obase + c;
            }
        }
        __syncthreads();

        // ---- Phase 3b: one scalar signs load per el (Weff == W * s_pre[e])
        if (tid < ECH)
            s_pre[tid] = signs[(size_t)(e0 + tid) * OO + s_idx[tid]];
        __syncthreads();

        #pragma unroll
        for (int el = 0; el < ECH; el++)
            coef[tid][el] *= s_pre[el];
        __syncthreads();

        // ---- Phase 4: PF-deep LDG pipeline over this task's worklist
        for (int i = 0; i < npad; i += PF) {
            #pragma unroll
            for (int j = 0; j < PF; j++) {
                const int k = i + j;
                const float4 dm = buf[j];
                buf[j] = __ldcs((const float4*)(dbase + wl_off[k + PF]));

                const uint32_t meta = wl_meta[k];
                unsigned bm = meta >> 6;
                if (bm) {                            // warp-uniform
                    const int el = meta & 3;
                    const int d  = (meta >> 2) & 15;
                    const float4 wv = weffs[el][tid];
                    const float t0 = wv.x * dm.x;
                    const float t1 = wv.y * dm.y;
                    const float t2 = wv.z * dm.z;
                    const float t3 = wv.w * dm.w;
                    const float* crow = &coef[d * BB][el];
                    while (bm) {                     // avg ~1.2 active batches
                        const int b = __ffs(bm) - 1;
                        bm &= bm - 1;
                        const float c = crow[b * ECH];
                        switch (b) {
                        case 0: acc[0].x += t0*c; acc[0].y += t1*c; acc[0].z += t2*c; acc[0].w += t3*c; break;
                        case 1: acc[1].x += t0*c; acc[1].y += t1*c; acc[1].z += t2*c; acc[1].w += t3*c; break;
                        case 2: acc[2].x += t0*c; acc[2].y += t1*c; acc[2].z += t2*c; acc[2].w += t3*c; break;
                        case 3: acc[3].x += t0*c; acc[3].y += t1*c; acc[3].z += t2*c; acc[3].w += t3*c; break;
                        case 4: acc[4].x += t0*c; acc[4].y += t1*c; acc[4].z += t2*c; acc[4].w += t3*c; break;
                        case 5: acc[5].x += t0*c; acc[5].y += t1*c; acc[5].z += t2*c; acc[5].w += t3*c; break;
                        case 6: acc[6].x += t0*c; acc[6].y += t1*c; acc[6].z += t2*c; acc[6].w += t3*c; break;
                        default: acc[7].x += t0*c; acc[7].y += t1*c; acc[7].z += t2*c; acc[7].w += t3*c; break;
                        }
                    }
                }
            }
        }
    }

    // ---- Single REDG epilogue per worker (acc accumulated over all its tasks)
    #pragma unroll
    for (int b = 0; b < BB; b++) {
        float* dst = out + b * OO + obase;
        asm volatile("red.global.add.v4.f32 [%0], {%1, %2, %3, %4};"
                     :: "l"(dst),
                        "f"(acc[b].x), "f"(acc[b].y), "f"(acc[b].z), "f"(acc[b].w)
                     : "memory");
    }
}

extern "C" void kernel_launch(void* const* d_in, const int* in_sizes, int n_in,
                              void* d_out, int out_size) {
    (void)in_sizes; (void)n_in; (void)out_size;
    const float* W      = (const float*)d_in[0];
    const float* signs  = (const float*)d_in[1];
    const float* Xd     = (const float*)d_in[2];
    const float* Wshort = (const float*)d_in[3];
    const float* dmap   = (const float*)d_in[4];
    float* out = (float*)d_out;

    zero_out<<<(BB * OO) / 256, 256>>>(out);
    dim3 grid(NWX, NOT);                          // 259 x 4 = 1036 persistent workers
    delta_synapse_main<<<grid, NTHREADS>>>(W, signs, Xd, Wshort, dmap, out);
}

// round 14
// speedup vs baseline: 1.1287x; 1.1287x over previous
#include <cuda_runtime.h>
#include <cstdint>

// Problem constants (fixed by the dataset)
#define DD 16
#define BB 8
#define EE 2048
#define OO 2048

#define ECH    8                 // e's per chunk
#define NCHUNK (EE / ECH)        // 256
#define NTHREADS 128
#define OTILE  (NTHREADS * 4)    // 512 o's per block
#define NOT    (OO / OTILE)      // 4
#define PF     4                 // prefetch pipeline depth (one uint4 group)

__global__ __launch_bounds__(256)
void zero_out(float* __restrict__ out) {
    out[blockIdx.x * 256 + threadIdx.x] = 0.0f;
}

__global__ __launch_bounds__(NTHREADS, 7)   // 148*7 = 1036 >= 1024 -> single wave
void delta_synapse_main(const float* __restrict__ W,
                        const float* __restrict__ signs,
                        const float* __restrict__ Xd,
                        const float* __restrict__ Wshort,
                        const float* __restrict__ dmap,
                        float* __restrict__ out) {
    __shared__ float    coef[DD * BB][ECH];        // 4 KB: signed Xd*(Wshort+1)
    __shared__ float4   weffs[ECH][NTHREADS];      // 8 KB: raw W slice
    __shared__ __align__(16) uint32_t wl_off [ECH * DD + 2 * PF];
    __shared__ __align__(16) uint32_t wl_meta[ECH * DD + 2 * PF];
    __shared__ int   s_idx[ECH];
    __shared__ float s_pre[ECH];
    __shared__ int wl_n;

    const int tid   = threadIdx.x;
    const int chunk = blockIdx.x;                  // 0..255
    const int otile = blockIdx.y;                  // 0..3
    const int e0    = chunk * ECH;
    const int obase = otile * OTILE + tid * 4;

    if (tid == 0) wl_n = 0;
    if (tid < ECH) s_idx[tid] = 0;
    __syncthreads();

    // ---- Phase 1: coef[d*8+b][el] = Xd * (Wshort + 1)  (1024 elems, 8/thread)
    #pragma unroll
    for (int r = 0; r < (DD * BB * ECH) / NTHREADS; r++) {
        const int idx = r * NTHREADS + tid;
        const int el  = idx & (ECH - 1);
        const int g   = idx >> 3;                   // d*8 + b
        const int gi  = g * EE + e0 + el;
        const float x = Xd[gi];
        coef[g][el] = x * (Wshort[gi] + 1.0f);
    }
    __syncthreads();

    // ---- Phase 2: one thread per (el,d) pair; warp-aggregated worklist append
    {
        const int el = tid & (ECH - 1);
        const int d  = tid >> 3;                    // 0..15
        unsigned bm = 0;
        #pragma unroll
        for (int b = 0; b < BB; b++)
            if (coef[d * BB + b][el] != 0.0f) bm |= 1u << b;
        const unsigned act  = __ballot_sync(0xffffffffu, bm != 0);
        const int      lane = tid & 31;
        int base = 0;
        if (lane == 0 && act) base = atomicAdd(&wl_n, __popc(act));
        base = __shfl_sync(0xffffffffu, base, 0);
        if (bm) {
            const int pos = base + __popc(act & ((1u << lane) - 1u));
            wl_off [pos] = (uint32_t)(d * EE + e0 + el) * OO;
            wl_meta[pos] = (uint32_t)(el | (d << 3) | (bm << 7));
        }
    }
    __syncthreads();

    // ---- Pad sentinels (off=0, bm=0 -> harmless no-ops)
    const int n0   = wl_n;
    const int npad = (n0 + PF - 1) & ~(PF - 1);    // multiple of 4 -> uint4 aligned
    if (tid < 2 * PF) { wl_off[n0 + tid] = 0u; wl_meta[n0 + tid] = 0u; }
    __syncthreads();

    // ---- Early dmap prefetch: first group flies concurrently with Phase 3
    const float* dbase = dmap + obase;
    float4 buf[PF];
    {
        const uint4 o4 = *(const uint4*)&wl_off[0];
        buf[0] = __ldcs((const float4*)(dbase + o4.x));
        buf[1] = __ldcs((const float4*)(dbase + o4.y));
        buf[2] = __ldcs((const float4*)(dbase + o4.z));
        buf[3] = __ldcs((const float4*)(dbase + o4.w));
    }

    // ---- Phase 3a: raw W into smem; record any positive-W o per el (racy OK)
    #pragma unroll
    for (int el = 0; el < ECH; el++) {
        const float4 wv = __ldcs((const float4*)&W[(size_t)(e0 + el) * OO + obase]);
        weffs[el][tid] = wv;
        if (wv.x > 0.f || wv.y > 0.f || wv.z > 0.f || wv.w > 0.f) {
            const int c = wv.x > 0.f ? 0 : (wv.y > 0.f ? 1 : (wv.z > 0.f ? 2 : 3));
            s_idx[el] = obase + c;                  // benign race: any winner valid
        }
    }
    __syncthreads();

    // ---- Phase 3b: one scalar signs load per el (Weff == W * s_pre[e]).
    if (tid < ECH)
        s_pre[tid] = signs[(size_t)(e0 + tid) * OO + s_idx[tid]];
    __syncthreads();

    // ---- Fold s_pre into coef so the hot loop is unchanged
    #pragma unroll
    for (int el = 0; el < ECH; el++)
        coef[tid][el] *= s_pre[el];
    __syncthreads();

    float4 acc[BB];
    #pragma unroll
    for (int b = 0; b < BB; b++) acc[b] = make_float4(0.f, 0.f, 0.f, 0.f);

    // ---- Phase 4: PF-deep pipeline. Per GROUP: one LDS.128 of next offsets +
    //      one LDS.128 of current metas -> every per-entry LDG and the decode
    //      depend only on registers (no LDS on the LDG critical path).
    for (int i = 0; i < npad; i += PF) {
        const uint4 o4 = *(const uint4*)&wl_off [i + PF];  // next group's offsets
        const uint4 m4 = *(const uint4*)&wl_meta[i];       // this group's metas
        #pragma unroll
        for (int j = 0; j < PF; j++) {
            const float4 dm = buf[j];

            const uint32_t offn = (j == 0) ? o4.x : (j == 1) ? o4.y
                                : (j == 2) ? o4.z : o4.w;
            buf[j] = __ldcs((const float4*)(dbase + offn));

            const uint32_t meta = (j == 0) ? m4.x : (j == 1) ? m4.y
                                : (j == 2) ? m4.z : m4.w;
            unsigned bm = meta >> 7;
            if (bm) {                               // warp-uniform; 0 only on sentinels
                const int el = meta & 7;
                const int d  = (meta >> 3) & 15;
                const float4 wv = weffs[el][tid];   // raw W; sign folded in coef
                const float t0 = wv.x * dm.x;
                const float t1 = wv.y * dm.y;
                const float t2 = wv.z * dm.z;
                const float t3 = wv.w * dm.w;
                const float* crow = &coef[d * BB][el];  // +b*ECH per batch
                while (bm) {                        // avg ~1.2 active batches
                    const int b = __ffs(bm) - 1;
                    bm &= bm - 1;
                    const float c = crow[b * ECH];  // smem broadcast
                    switch (b) {                    // static acc indexing
                    case 0: acc[0].x += t0*c; acc[0].y += t1*c; acc[0].z += t2*c; acc[0].w += t3*c; break;
                    case 1: acc[1].x += t0*c; acc[1].y += t1*c; acc[1].z += t2*c; acc[1].w += t3*c; break;
                    case 2: acc[2].x += t0*c; acc[2].y += t1*c; acc[2].z += t2*c; acc[2].w += t3*c; break;
                    case 3: acc[3].x += t0*c; acc[3].y += t1*c; acc[3].z += t2*c; acc[3].w += t3*c; break;
                    case 4: acc[4].x += t0*c; acc[4].y += t1*c; acc[4].z += t2*c; acc[4].w += t3*c; break;
                    case 5: acc[5].x += t0*c; acc[5].y += t1*c; acc[5].z += t2*c; acc[5].w += t3*c; break;
                    case 6: acc[6].x += t0*c; acc[6].y += t1*c; acc[6].z += t2*c; acc[6].w += t3*c; break;
                    default: acc[7].x += t0*c; acc[7].y += t1*c; acc[7].z += t2*c; acc[7].w += t3*c; break;
                    }
                }
            }
        }
    }

    // ---- Phase 5: reduce directly into out via vector REDG (no return value).
    #pragma unroll
    for (int b = 0; b < BB; b++) {
        float* dst = out + b * OO + obase;
        asm volatile("red.global.add.v4.f32 [%0], {%1, %2, %3, %4};"
                     :: "l"(dst),
                        "f"(acc[b].x), "f"(acc[b].y), "f"(acc[b].z), "f"(acc[b].w)
                     : "memory");
    }
}

extern "C" void kernel_launch(void* const* d_in, const int* in_sizes, int n_in,
                              void* d_out, int out_size) {
    (void)in_sizes; (void)n_in; (void)out_size;
    const float* W      = (const float*)d_in[0];
    const float* signs  = (const float*)d_in[1];
    const float* Xd     = (const float*)d_in[2];
    const float* Wshort = (const float*)d_in[3];
    const float* dmap   = (const float*)d_in[4];
    float* out = (float*)d_out;

    zero_out<<<(BB * OO) / 256, 256>>>(out);
    dim3 grid(NCHUNK, NOT);                       // 256 x 4 = 1024 blocks, 1 wave
    delta_synapse_main<<<grid, NTHREADS>>>(W, signs, Xd, Wshort, dmap, out);
}